// round 6
// baseline (speedup 1.0000x reference)
#include <cuda_runtime.h>
#include <cstdint>

// L1Attn: out[b,i,j,h] = -(1/8) * sum_d |q[b,j,h,d] - k[b,i,h,d]|
// B=8, S=1024, H=8, D=64. Output [B,S,S,H] (i = keys, j = queries).
//
// Block: 8 i x 128 j x 8 h. Thread: one h, 8 i x 4 j outputs, packed f32x2.
// k tile + q tile both staged in smem with conflict-free padded layouts;
// q staged in 4 chunks of 16 d to fit smem (2 blocks/SM).

namespace {
constexpr int S  = 1024;
constexpr int H  = 8;
constexpr int D  = 64;
constexpr int NT = 256;
constexpr int TI = 8;     // i per block
constexpr int JB = 128;   // j per block
constexpr int KROW = 68;  // k row: 64 d + 4 pad floats (h-rows on distinct quads)
constexpr int QROW = 20;  // q row: 16 d + 4 pad floats (5*row mod 8 covers quads)
constexpr int KS_FLOATS = TI * H * KROW;   // 4352  (17408 B)
constexpr int QS_FLOATS = JB * H * QROW;   // 20480 (81920 B)
constexpr unsigned SMEM_BYTES = (KS_FLOATS + QS_FLOATS) * 4;  // 99328

typedef unsigned long long ull;

__device__ __forceinline__ ull addx2(ull a, ull b) {
    ull r;
    asm("add.rn.f32x2 %0, %1, %2;" : "=l"(r) : "l"(a), "l"(b));
    return r;
}
}  // namespace

__global__ void __launch_bounds__(NT, 2) l1attn_kernel(
    const float* __restrict__ qg,
    const float* __restrict__ kg,
    float* __restrict__ out)
{
    extern __shared__ __align__(16) float smf[];
    float* ks = smf;                // [64 rows][68]
    float* qs = smf + KS_FLOATS;    // [1024 rows][20], rows = jj*8 + h, 16 d/chunk

    const int t  = threadIdx.x;
    const int j0 = blockIdx.x * JB;
    const int i0 = blockIdx.y * TI;
    const int b  = blockIdx.z;

    // ---- Stage k tile: rows (ii*8 + h), 64 floats each ----
    {
        const float* kb = kg + ((size_t)b * S + i0) * (size_t)(H * D);
        #pragma unroll
        for (int r = 0; r < (TI * H * D) / (4 * NT); r++) {  // 4 iters
            int idx = t + r * NT;
            int row = idx >> 4;
            int dd  = (idx & 15) << 2;
            float4 v = *reinterpret_cast<const float4*>(kb + row * D + dd);
            *reinterpret_cast<float4*>(&ks[row * KROW + dd]) = v;
        }
    }

    const int h  = t & 7;
    const int jl = (t >> 3) & 3;
    const int w  = t >> 5;
    const int jbase = j0 + w * 16 + jl;          // u stride = 4 j
    const int qrow0 = (w * 16 + jl) * 8 + h;     // u adds 4 j = 32 rows

    const ull SGN = 0x8000000080000000ULL;
    const ull MSK = 0x7FFFFFFF7FFFFFFFULL;

    // q global base for this block (row r of tile = floats r*64 within tile)
    const float* qtile = qg + ((size_t)b * S + j0) * (size_t)(H * D);

    ull acc[TI][4];
    #pragma unroll
    for (int i = 0; i < TI; i++)
        #pragma unroll
        for (int u = 0; u < 4; u++) acc[i][u] = 0ULL;

    // ---- Stage q chunk 0 (d 0..15) ----
    #pragma unroll
    for (int r = 0; r < 16; r++) {
        int p   = t + r * NT;      // piece 0..4095
        int row = p >> 2;          // 0..1023
        int sg  = p & 3;           // 16B seg within chunk
        float4 v = *reinterpret_cast<const float4*>(qtile + row * D + sg * 4);
        *reinterpret_cast<float4*>(&qs[row * QROW + sg * 4]) = v;
    }
    __syncthreads();

    #pragma unroll 1
    for (int cc = 0; cc < 4; cc++) {           // d-chunk of 16
        // ---- Compute on chunk cc ----
        #pragma unroll 1
        for (int s = 0; s < 4; s++) {          // 4 d per step
            ull nq[4][2];
            #pragma unroll
            for (int u = 0; u < 4; u++) {
                ulonglong2 qv = *reinterpret_cast<const ulonglong2*>(
                    qs + (qrow0 + u * 32) * QROW + s * 4);   // u: +4 j = +32 rows
                nq[u][0] = qv.x ^ SGN;
                nq[u][1] = qv.y ^ SGN;
            }
            const float* kr = ks + h * KROW + cc * 16 + s * 4;
            #pragma unroll
            for (int i = 0; i < TI; i++) {
                ulonglong2 kv = *reinterpret_cast<const ulonglong2*>(kr + i * (8 * KROW));
                #pragma unroll
                for (int u = 0; u < 4; u++) {
                    ull t0 = addx2(kv.x, nq[u][0]) & MSK;   // |k-q| d pair 0
                    ull t1 = addx2(kv.y, nq[u][1]) & MSK;   // d pair 1
                    acc[i][u] = addx2(acc[i][u], addx2(t0, t1));
                }
            }
        }
        // ---- Stage next q chunk ----
        if (cc < 3) {
            __syncthreads();   // all reads of current chunk done
            const float* qc = qtile + (cc + 1) * 16;
            #pragma unroll
            for (int r = 0; r < 16; r++) {
                int p   = t + r * NT;
                int row = p >> 2;
                int sg  = p & 3;
                float4 v = *reinterpret_cast<const float4*>(qc + row * D + sg * 4);
                *reinterpret_cast<float4*>(&qs[row * QROW + sg * 4]) = v;
            }
            __syncthreads();
        }
    }

    // ---- Epilogue: reduce packed halves, scale, coalesced stores ----
    const float scale = -0.125f;  // -1/sqrt(64)
    #pragma unroll
    for (int i = 0; i < TI; i++) {
        const size_t ob = (((size_t)b * S + (i0 + i)) * S + jbase) * H + h;
        #pragma unroll
        for (int u = 0; u < 4; u++) {
            unsigned int lo = (unsigned int)(acc[i][u] & 0xffffffffu);
            unsigned int hi = (unsigned int)(acc[i][u] >> 32);
            out[ob + (size_t)u * (4 * H)] =
                (__uint_as_float(lo) + __uint_as_float(hi)) * scale;
        }
    }
}

extern "C" void kernel_launch(void* const* d_in, const int* in_sizes, int n_in,
                              void* d_out, int out_size) {
    const float* q = (const float*)d_in[0];
    const float* k = (const float*)d_in[1];
    float* out     = (float*)d_out;

    cudaFuncSetAttribute(l1attn_kernel,
                         cudaFuncAttributeMaxDynamicSharedMemorySize, SMEM_BYTES);

    const int B = in_sizes[0] / (S * H * D);  // = 8
    dim3 grid(S / JB, S / TI, B);
    l1attn_kernel<<<grid, NT, SMEM_BYTES>>>(q, k, out);
}